// round 15
// baseline (speedup 1.0000x reference)
#include <cuda_runtime.h>
#include <cstdint>

#define MAXN 10000
#define MAXE 640000
#define NH   48
#define NG   192
#define KPRE 64            // sequential H-prefix length (splice horizon)
#define BURN 48            // chunk burn-in
#define CHL  24            // chunk output length
#define MAXROWS (BURN + CHL)   // 72 = max rows a chunk block owns
#define CDIV(a,b) (((a)+(b)-1)/(b))

// ---------------- scratch (static device memory; no allocations) ----------------
__device__ int   g_flags[2];
__device__ int   g_srcH[MAXE], g_dstH[MAXE], g_srcW[MAXE], g_dstW[MAXE];
__device__ int   g_idegH[MAXN], g_idegW[MAXN];
__device__ int   g_offH[MAXN + 1], g_offW[MAXN + 1];
__device__ int   g_curH[MAXN], g_curW[MAXN];
__device__ int   g_csrH[MAXE], g_csrW[MAXE];
__device__ int   g_syncH[2], g_syncW[2];
__device__ int   g_citer;
__device__ float g_dinvH[MAXN], g_dinvW[MAXN];
__device__ float g_hs12[MAXN * 12];    // H * dinvH, padded to 12 (cols 10,11 = 0)
__device__ float g_ws12[MAXN * 12];    // Wout * dinvW, padded to 12
__device__ float g_x2s[MAXN * 16];     // H-branch layer-1 out, pre-scaled by dinv
__device__ float g_x2sb[MAXN * 16];    // W-branch layer-1 out, pre-scaled by dinv
__device__ float g_xgH[MAXN * 192];
__device__ float g_xgW[MAXN * 192];
__device__ float g_dproj[MAXN * 10];
__device__ float g_state0[2 * NH];
__device__ float g_stateHend[2 * NH];
__device__ float g_stateArr[10 * 2 * NH];

// ---------------- math helpers ----------------
__device__ __forceinline__ float tanh_fast(float x) {
    float y;
    asm("tanh.approx.f32 %0, %1;" : "=f"(y) : "f"(x));
    return y;
}
__device__ __forceinline__ float fsig(float x) {
    return __fdividef(1.f, 1.f + __expf(-x));
}
__device__ __forceinline__ float ftanh(float x) {
    return __fdividef(2.f, 1.f + __expf(-2.f * x)) - 1.f;
}

// ---------------- setup kernels ----------------
__global__ void detect_zero_kernel(const unsigned* ha, const unsigned* wa, int E, int* flags,
                                   int* idegH, int* idegW, float* st0, int M, int N) {
    __shared__ int sH, sW;
    int t = threadIdx.x;
    if (t == 0) { sH = 0; sW = 0; }
    __syncthreads();
    int lim = E < 2048 ? E : 2048;
    for (int i = t; i < lim; i += 256) {
        if (ha[2 * i + 1]) atomicOr(&sH, 1);
        if (wa[2 * i + 1]) atomicOr(&sW, 1);
    }
    for (int i = t; i < M; i += 256) idegH[i] = 0;
    for (int i = t; i < N; i += 256) idegW[i] = 0;
    if (t < 96) st0[t] = 0.f;
    __syncthreads();
    if (t == 0) { flags[0] = sH; flags[1] = sW; }
}

__global__ void cvt_deg_kernel(const void* __restrict__ raw, int* __restrict__ src,
                               int* __restrict__ dst, int* __restrict__ deg,
                               int E, const int* __restrict__ flag) {
    int e = blockIdx.x * blockDim.x + threadIdx.x;
    if (e >= E) return;
    int s, d;
    if (*flag) {
        const int* p = (const int*)raw;
        s = p[e]; d = p[E + e];
    } else {
        const long long* p = (const long long*)raw;
        s = (int)p[e]; d = (int)p[E + e];
    }
    src[e] = s; dst[e] = d;
    atomicAdd(&deg[d], 1);
}

__global__ void scan_dinv_kernel(const int* __restrict__ deg, int* __restrict__ off,
                                 int* __restrict__ cur, float* __restrict__ dinv, int n) {
    __shared__ int part[1024];
    int tid = threadIdx.x;
    int chunk = (n + 1023) / 1024;
    int base = tid * chunk;
    int s = 0;
    for (int k = 0; k < chunk; k++) {
        int i = base + k;
        if (i < n) s += deg[i];
    }
    part[tid] = s;
    __syncthreads();
    for (int d = 1; d < 1024; d <<= 1) {
        int v = (tid >= d) ? part[tid - d] : 0;
        __syncthreads();
        part[tid] += v;
        __syncthreads();
    }
    int run = (tid == 0) ? 0 : part[tid - 1];
    for (int k = 0; k < chunk; k++) {
        int i = base + k;
        if (i < n) {
            off[i] = run; cur[i] = run; run += deg[i];
            dinv[i] = rsqrtf((float)deg[i] + 1.f);
        }
    }
    if (tid == 1023) off[n] = part[1023];
}

__global__ void csrfill_kernel(const int* __restrict__ src, const int* __restrict__ dst,
                               int* __restrict__ cur, int* __restrict__ csr, int E) {
    int e = blockIdx.x * blockDim.x + threadIdx.x;
    if (e >= E) return;
    int p = atomicAdd(&cur[dst[e]], 1);
    csr[p] = src[e];
}

// scale x[n,10] by dinv into padded [n,12] (cols 10,11 zero)
__global__ void scale12_kernel(const float* __restrict__ x, const float* __restrict__ dinv,
                               float* __restrict__ xs, int n) {
    int idx = blockIdx.x * blockDim.x + threadIdx.x;
    if (idx >= n * 12) return;
    int r = idx / 12, c = idx - r * 12;
    xs[idx] = (c < 10) ? x[r * 10 + c] * dinv[r] : 0.f;
}

// ---- fused full GCN chain, float4 pre-scaled gathers, spin-barrier between layers ----
// Blocks [0, nb1): layer-1 on 16 nodes each (16 thr/node: 4 quads x 4 edge-slices).
// Blocks [nb1, nb1+nb1): layer-2 + xg on 16 nodes each.
__global__ void __launch_bounds__(256)
gcn_fused_kernel(const int* __restrict__ off, const int* __restrict__ csr,
                 const float* __restrict__ dinv,
                 const float* __restrict__ xs,    // [n,12] pre-scaled input
                 const float* __restrict__ w0, const float* __restrict__ b0,
                 float* __restrict__ x2s,         // [n,16] pre-scaled layer-1 out
                 const float* __restrict__ w1, const float* __restrict__ b1,
                 const float* __restrict__ wih, const float* __restrict__ bi,
                 const float* __restrict__ bh, float* __restrict__ xg,
                 int n, int nb1, int* __restrict__ sync) {
    __shared__ __align__(16) float4 part4[16 * 16];   // [node][q*4+sl]
    __shared__ float agg1[16][12];
    __shared__ float agg2[16][17];                    // padded row
    __shared__ __align__(16) float t_sh[16][NH];
    int bid = blockIdx.x;
    int t = threadIdx.x;
    int nd = t >> 4, tt = t & 15;
    int q = tt & 3, sl = tt >> 2;

    if (bid < nb1) {
        // ---- layer 1: gather(12ch f4) + GEMM 10->16, out pre-scaled ----
        int d = bid * 16 + nd;
        float4 acc = make_float4(0.f, 0.f, 0.f, 0.f);
        if (d < n && q < 3) {
            int e0 = off[d], e1 = off[d + 1];
            for (int e = e0 + sl; e < e1; e += 4) {
                int s = csr[e];
                float4 v = *(const float4*)(xs + s * 12 + q * 4);
                acc.x += v.x; acc.y += v.y; acc.z += v.z; acc.w += v.w;
            }
        }
        part4[nd * 16 + q * 4 + sl] = acc;
        __syncthreads();
        if (t < 192) {
            int nd2 = t / 12, c = t - (t / 12) * 12;
            int d2 = bid * 16 + nd2;
            if (d2 < n) {
                int q2 = c >> 2, l = c & 3;
                const float* pf = (const float*)part4;
                int base = (nd2 * 16 + q2 * 4) * 4 + l;
                float s = pf[base] + pf[base + 4] + pf[base + 8] + pf[base + 12];
                float dd = dinv[d2];
                s += xs[d2 * 12 + c] * dd;     // self term (xs already has one dinv)
                agg1[nd2][c] = s * dd;
            }
        }
        __syncthreads();
        {
            int d3 = bid * 16 + nd;           // nd = t>>4, tt = c2
            if (d3 < n) {
                float s = b0[tt];
#pragma unroll
                for (int k = 0; k < 10; k++) s = fmaf(agg1[nd][k], w0[k * 16 + tt], s);
                x2s[d3 * 16 + tt] = s * dinv[d3];
            }
        }
        __threadfence();
        __syncthreads();
        if (t == 0) atomicAdd(&sync[0], 1);
        return;
    }

    // ---- layer 2 + xg ----
    int g = bid - nb1;
    if (t == 0) {
        while (atomicAdd(&sync[0], 0) < nb1) __nanosleep(64);
    }
    __syncthreads();

    int r = g * 16 + nd;
    float4 acc = make_float4(0.f, 0.f, 0.f, 0.f);
    if (r < n) {
        int e0 = off[r], e1 = off[r + 1];
        for (int e = e0 + sl; e < e1; e += 4) {
            int s = csr[e];
            float4 v = *(const float4*)(x2s + s * 16 + q * 4);
            acc.x += v.x; acc.y += v.y; acc.z += v.z; acc.w += v.w;
        }
    }
    part4[nd * 16 + q * 4 + sl] = acc;
    __syncthreads();
    {
        // agg2[nd][c], c = tt (16 channels)
        int r2 = g * 16 + nd;
        if (r2 < n) {
            int q2 = tt >> 2, l = tt & 3;
            const float* pf = (const float*)part4;
            int base = (nd * 16 + q2 * 4) * 4 + l;
            float s = pf[base] + pf[base + 4] + pf[base + 8] + pf[base + 12];
            float dd = dinv[r2];
            s += x2s[r2 * 16 + tt] * dd;       // self term
            agg2[nd][tt] = s * dd;
        }
    }
    __syncthreads();
    // tilde = sigmoid(agg2 @ w1 + b1): 16*48 = 768 outputs
    for (int o = t; o < 768; o += 256) {
        int nd2 = o / 48, jj = o - (o / 48) * 48;
        int rr = g * 16 + nd2;
        if (rr < n) {
            float s = b1[jj];
#pragma unroll
            for (int k = 0; k < 16; k++) s = fmaf(agg2[nd2][k], w1[k * NH + jj], s);
            t_sh[nd2][jj] = fsig(s);
        }
    }
    __syncthreads();
    // xg = tilde @ Wih^T (+biases, gate-fold): 16*192 = 3072 outputs
    for (int o = t; o < 3072; o += 256) {
        int nd2 = o / 192, j = o - (o / 192) * 192;
        int rr = g * 16 + nd2;
        if (rr >= n) continue;
        const float4* a = (const float4*)t_sh[nd2];
        const float4* w = (const float4*)(wih + j * NH);
        float s = 0.f;
#pragma unroll
        for (int k = 0; k < 12; k++) {
            float4 av = a[k], wv = w[k];
            s = fmaf(av.x, wv.x, s); s = fmaf(av.y, wv.y, s);
            s = fmaf(av.z, wv.z, s); s = fmaf(av.w, wv.w, s);
        }
        float fac = (j >= 96 && j < 144) ? 1.f : 0.5f;
        xg[rr * NG + j] = (s + bi[j] + bh[j]) * fac;
    }
    if (t == 0) {
        int d = atomicAdd(&sync[1], 1);
        if (d == nb1 - 1) { sync[0] = 0; sync[1] = 0; }
    }
}

__global__ void tail_kernel(float* __restrict__ out, const float* __restrict__ dproj,
                            int from, int total) {
    int i = from + blockIdx.x * blockDim.x + threadIdx.x;
    if (i < total) out[i] += 9.f * dproj[i];
}

// ---------------- f32x2 helpers ----------------
__device__ __forceinline__ unsigned long long pack2(float lo, float hi) {
    unsigned long long r;
    unsigned a = __float_as_uint(lo), b = __float_as_uint(hi);
    asm("mov.b64 %0, {%1, %2};" : "=l"(r) : "r"(a), "r"(b));
    return r;
}
__device__ __forceinline__ void unpack2(unsigned long long v, float& lo, float& hi) {
    unsigned a, b;
    asm("mov.b64 {%0, %1}, %2;" : "=r"(a), "=r"(b) : "l"(v));
    lo = __uint_as_float(a); hi = __uint_as_float(b);
}
__device__ __forceinline__ unsigned long long fma2(unsigned long long a,
                                                   unsigned long long b,
                                                   unsigned long long c) {
    unsigned long long d;
    asm("fma.rn.f32x2 %0, %1, %2, %3;" : "=l"(d) : "l"(a), "l"(b), "l"(c));
    return d;
}
__device__ __forceinline__ unsigned long long add2(unsigned long long a,
                                                   unsigned long long b) {
    unsigned long long d;
    asm("add.rn.f32x2 %0, %1, %2;" : "=l"(d) : "l"(a), "l"(b));
    return d;
}

// ---------------- shared LSTM step body ----------------
struct LstmCtx {
    unsigned long long w2[24];
    unsigned hs;
    int aoff;
    bool is_g;
};

__device__ __forceinline__ void lstm_load_weights(LstmCtx& cx, const float* whh,
                                                  float* h_sh, int j) {
    cx.is_g = (j >= 96 && j < 144);
    float wfac = cx.is_g ? 1.f : 0.5f;
    cx.aoff = (j % 48) * 4 + (j / 48);
#pragma unroll
    for (int p = 0; p < 24; p++)
        cx.w2[p] = pack2(whh[j * NH + 2 * p] * wfac, whh[j * NH + 2 * p + 1] * wfac);
    asm("{ .reg .u64 t; cvta.to.shared.u64 t, %1; cvt.u32.u64 %0, t; }"
        : "=r"(cx.hs) : "l"((void*)h_sh));
}

__device__ __forceinline__ float lstm_gate(const LstmCtx& cx, float xcur) {
    unsigned long long acc[8];
#pragma unroll
    for (int q = 0; q < 8; q++) acc[q] = 0ull;
#pragma unroll
    for (int k = 0; k < 3; k++) {
        unsigned long long hp[8];
        asm volatile("ld.shared.v2.u64 {%0, %1}, [%2];"
                     : "=l"(hp[0]), "=l"(hp[1]) : "r"(cx.hs + k * 64));
        asm volatile("ld.shared.v2.u64 {%0, %1}, [%2];"
                     : "=l"(hp[2]), "=l"(hp[3]) : "r"(cx.hs + k * 64 + 16));
        asm volatile("ld.shared.v2.u64 {%0, %1}, [%2];"
                     : "=l"(hp[4]), "=l"(hp[5]) : "r"(cx.hs + k * 64 + 32));
        asm volatile("ld.shared.v2.u64 {%0, %1}, [%2];"
                     : "=l"(hp[6]), "=l"(hp[7]) : "r"(cx.hs + k * 64 + 48));
#pragma unroll
        for (int q = 0; q < 8; q++)
            acc[q] = fma2(cx.w2[k * 8 + q], hp[q], acc[q]);
    }
    acc[0] = add2(acc[0], acc[1]);
    acc[2] = add2(acc[2], acc[3]);
    acc[4] = add2(acc[4], acc[5]);
    acc[6] = add2(acc[6], acc[7]);
    acc[0] = add2(acc[0], acc[2]);
    acc[4] = add2(acc[4], acc[6]);
    acc[0] = add2(acc[0], acc[4]);
    float s0, s1;
    unpack2(acc[0], s0, s1);
    float g = s0 + s1 + xcur;
    float th = tanh_fast(g);
    return cx.is_g ? th : fmaf(0.5f, th, 0.5f);
}

// dense epilogue from SHARED ys; optionally maintains ws = out*dinv (padded 12)
__device__ __forceinline__ void dense_epilogue_sh(const float* __restrict__ ys_sh,
                                                  const float* __restrict__ dw,
                                                  const float* __restrict__ db,
                                                  float* __restrict__ out,
                                                  float* __restrict__ dproj,
                                                  float* __restrict__ ws,
                                                  const float* __restrict__ dinv,
                                                  int r0, int r1, int j) {
    for (int idx = r0 * 10 + j; idx < r1 * 10; idx += 192) {
        int r = idx / 10, c = idx - r * 10;
        const float4* a = (const float4*)(ys_sh + (r - r0) * NH);
        const float4* w = (const float4*)(dw + c * NH);
        float s = 0.f;
#pragma unroll
        for (int k = 0; k < 12; k++) {
            float4 av = a[k], wv = w[k];
            s = fmaf(av.x, wv.x, s); s = fmaf(av.y, wv.y, s);
            s = fmaf(av.z, wv.z, s); s = fmaf(av.w, wv.w, s);
        }
        float v = ftanh(s + db[c]);
        if (dproj) dproj[idx] = v;
        float nv = out[idx] + v;
        out[idx] = nv;
        if (ws) ws[r * 12 + c] = nv * dinv[r];
    }
}

// ---------------- chunked parallel LSTM scan, ys in shared, fused dense ----------------
__global__ void __launch_bounds__(192)
lstm_chunk_kernel(const float* __restrict__ xg, const float* __restrict__ whh,
                  const float* __restrict__ state_in, float* __restrict__ state_out,
                  int S, int L, int B,
                  const float* __restrict__ dw, const float* __restrict__ db,
                  float* __restrict__ out, float* __restrict__ dproj,
                  float* __restrict__ ws, const float* __restrict__ dinv, int flagval) {
    __shared__ __align__(16) float h_sh[NH];
    __shared__ __align__(16) float a_sh[NG];
    __shared__ __align__(16) float ys_sh[MAXROWS * NH];
    const int j = threadIdx.x;
    const int i = blockIdx.x;

    const int OUT0 = B + L;
    int ostart = (i == 0) ? 0 : OUT0 + (i - 1) * L;
    int t0 = (i == 0) ? 0 : ostart - B;
    int oend = (i == 0) ? OUT0 : ostart + L;
    if (oend > S) oend = S;

    LstmCtx cx;
    lstm_load_weights(cx, whh, h_sh, j);

    float c = 0.f;
    if (j < NH) {
        float hv = 0.f;
        if (i == 0) { hv = state_in[j]; c = state_in[NH + j]; }
        h_sh[j] = hv;
    }
    __syncthreads();

    float xcur = xg[t0 * NG + j];
    for (int t = t0; t < oend; t++) {
        float xnext = 0.f;
        if (t + 1 < oend) xnext = __ldg(&xg[(t + 1) * NG + j]);
        float a = lstm_gate(cx, xcur);
        xcur = xnext;
        a_sh[cx.aoff] = a;
        __syncthreads();
        if (j < NH) {
            float4 gv = *(const float4*)(a_sh + j * 4);
            c = fmaf(gv.y, c, gv.x * gv.z);
            float hn = gv.w * tanh_fast(c);
            h_sh[j] = hn;
            if (t >= ostart) ys_sh[(t - ostart) * NH + j] = hn;
        }
        __syncthreads();
    }
    if (oend == S && j < NH) { state_out[j] = h_sh[j]; state_out[NH + j] = c; }
    __syncthreads();
    if (oend == S && j == 0 && flagval > 0) {
        __threadfence();
        atomicExch(&g_citer, flagval);
    }
    dense_epilogue_sh(ys_sh, dw, db, out, dproj, ws, dinv, ostart, oend, j);
}

// ---------------- persistent H-prefix kernel: 1 block, consumes flags 1..9 ----------------
__global__ void __launch_bounds__(192, 1)
prefix_persist_kernel(const float* __restrict__ xgH, const float* __restrict__ whh,
                      const float* __restrict__ stateArr,
                      const float* __restrict__ dw, const float* __restrict__ db,
                      float* __restrict__ out, int K) {
    __shared__ __align__(16) float h_sh[NH];
    __shared__ __align__(16) float a_sh[NG];
    __shared__ __align__(16) float ys_sh[KPRE * NH];
    const int j = threadIdx.x;

    LstmCtx cx;
    lstm_load_weights(cx, whh, h_sh, j);

    for (int pit = 0; pit < 9; pit++) {
        if (j == 0) {
            while (atomicAdd(&g_citer, 0) < pit + 1) __nanosleep(128);
            __threadfence();
        }
        __syncthreads();
        const float* st = stateArr + pit * 2 * NH;
        float c = 0.f;
        if (j < NH) { h_sh[j] = __ldcg(&st[j]); c = __ldcg(&st[NH + j]); }
        __syncthreads();

        float xcur = __ldg(&xgH[j]);
        for (int t = 0; t < K; t++) {
            float xnext = 0.f;
            if (t + 1 < K) xnext = __ldg(&xgH[(t + 1) * NG + j]);
            float a = lstm_gate(cx, xcur);
            xcur = xnext;
            a_sh[cx.aoff] = a;
            __syncthreads();
            if (j < NH) {
                float4 gv = *(const float4*)(a_sh + j * 4);
                c = fmaf(gv.y, c, gv.x * gv.z);
                float hn = gv.w * tanh_fast(c);
                h_sh[j] = hn;
                ys_sh[t * NH + j] = hn;
            }
            __syncthreads();
        }
        dense_epilogue_sh(ys_sh, dw, db, out, nullptr, nullptr, nullptr, 0, K, j);
        __syncthreads();
    }
    if (j == 0) atomicExch(&g_citer, 0);
}

// ---------------- symbol address / stream / event cache ----------------
struct Sym {
    int* flags; int *srcH, *dstH, *srcW, *dstW;
    int *idegH, *idegW, *offH, *offW, *curH, *curW, *csrH, *csrW;
    int *syncH, *syncW;
    float *dinvH, *dinvW;
    float *hs12, *ws12, *x2s, *x2sb;
    float *xgH, *xgW;
    float *dproj, *state0, *stateHend, *stateArr;
    cudaStream_t side;
    cudaEvent_t evF, evJ, evP;
    bool ok;
};
static Sym S_ = {};

static void init_syms() {
    if (S_.ok) return;
    cudaGetSymbolAddress((void**)&S_.flags, g_flags);
    cudaGetSymbolAddress((void**)&S_.srcH, g_srcH);
    cudaGetSymbolAddress((void**)&S_.dstH, g_dstH);
    cudaGetSymbolAddress((void**)&S_.srcW, g_srcW);
    cudaGetSymbolAddress((void**)&S_.dstW, g_dstW);
    cudaGetSymbolAddress((void**)&S_.idegH, g_idegH);
    cudaGetSymbolAddress((void**)&S_.idegW, g_idegW);
    cudaGetSymbolAddress((void**)&S_.offH, g_offH);
    cudaGetSymbolAddress((void**)&S_.offW, g_offW);
    cudaGetSymbolAddress((void**)&S_.curH, g_curH);
    cudaGetSymbolAddress((void**)&S_.curW, g_curW);
    cudaGetSymbolAddress((void**)&S_.csrH, g_csrH);
    cudaGetSymbolAddress((void**)&S_.csrW, g_csrW);
    cudaGetSymbolAddress((void**)&S_.syncH, g_syncH);
    cudaGetSymbolAddress((void**)&S_.syncW, g_syncW);
    cudaGetSymbolAddress((void**)&S_.dinvH, g_dinvH);
    cudaGetSymbolAddress((void**)&S_.dinvW, g_dinvW);
    cudaGetSymbolAddress((void**)&S_.hs12, g_hs12);
    cudaGetSymbolAddress((void**)&S_.ws12, g_ws12);
    cudaGetSymbolAddress((void**)&S_.x2s, g_x2s);
    cudaGetSymbolAddress((void**)&S_.x2sb, g_x2sb);
    cudaGetSymbolAddress((void**)&S_.xgH, g_xgH);
    cudaGetSymbolAddress((void**)&S_.xgW, g_xgW);
    cudaGetSymbolAddress((void**)&S_.dproj, g_dproj);
    cudaGetSymbolAddress((void**)&S_.state0, g_state0);
    cudaGetSymbolAddress((void**)&S_.stateHend, g_stateHend);
    cudaGetSymbolAddress((void**)&S_.stateArr, g_stateArr);
    int* pcit; cudaGetSymbolAddress((void**)&pcit, g_citer);
    cudaMemset(pcit, 0, sizeof(int));
    cudaMemset(S_.syncH, 0, 2 * sizeof(int));
    cudaMemset(S_.syncW, 0, 2 * sizeof(int));
    cudaStreamCreateWithFlags(&S_.side, cudaStreamNonBlocking);
    cudaEventCreateWithFlags(&S_.evF, cudaEventDisableTiming);
    cudaEventCreateWithFlags(&S_.evJ, cudaEventDisableTiming);
    cudaEventCreateWithFlags(&S_.evP, cudaEventDisableTiming);
    S_.ok = true;
}

// ---------------- launch ----------------
extern "C" void kernel_launch(void* const* d_in, const int* in_sizes, int n_in,
                              void* d_out, int out_size) {
    init_syms();

    const float* H  = (const float*)d_in[0];
    const float* W  = (const float*)d_in[1];
    const void*  HA = d_in[2];
    const void*  WA = d_in[3];
    const float* hg0w = (const float*)d_in[4];
    const float* hg0b = (const float*)d_in[5];
    const float* hg1w = (const float*)d_in[6];
    const float* hg1b = (const float*)d_in[7];
    const float* wg0w = (const float*)d_in[8];
    const float* wg0b = (const float*)d_in[9];
    const float* wg1w = (const float*)d_in[10];
    const float* wg1b = (const float*)d_in[11];
    const float* Wih  = (const float*)d_in[12];
    const float* Whh  = (const float*)d_in[13];
    const float* bih  = (const float*)d_in[14];
    const float* bhh  = (const float*)d_in[15];
    const float* dHw  = (const float*)d_in[16];
    const float* dHb  = (const float*)d_in[17];
    const float* dWw  = (const float*)d_in[18];
    const float* dWb  = (const float*)d_in[19];

    const int M = in_sizes[0] / 10;
    const int N = in_sizes[1] / 10;
    const int E = in_sizes[2] / 2;
    const int K = (KPRE < M) ? KPRE : M;

    float* Hout = (float*)d_out;
    float* Wout = (float*)d_out + M * 10;

    const int B = 256;
    dim3 gE(CDIV(E, B));
    cudaStream_t sd = S_.side;

    const int CM = (M <= BURN + CHL) ? 1 : 1 + CDIV(M - (BURN + CHL), CHL);
    const int CN = (N <= BURN + CHL) ? 1 : 1 + CDIV(N - (BURN + CHL), CHL);
    const int nb1H = CDIV(M, 16), nb1W = CDIV(N, 16);

    // --- detect + zero, then split setup across streams ---
    detect_zero_kernel<<<1, 256>>>((const unsigned*)HA, (const unsigned*)WA, E, S_.flags,
                                   S_.idegH, S_.idegW, S_.state0, M, N);
    cudaEventRecord(S_.evF, 0);
    cudaStreamWaitEvent(sd, S_.evF, 0);

    // side stream: W setup + W-GCN(0)
    cvt_deg_kernel<<<gE, B, 0, sd>>>(WA, S_.srcW, S_.dstW, S_.idegW, E, S_.flags + 1);
    scan_dinv_kernel<<<1, 1024, 0, sd>>>(S_.idegW, S_.offW, S_.curW, S_.dinvW, N);
    csrfill_kernel<<<gE, B, 0, sd>>>(S_.srcW, S_.dstW, S_.curW, S_.csrW, E);
    cudaMemcpyAsync(Wout, W, (size_t)N * 10 * sizeof(float), cudaMemcpyDeviceToDevice, sd);
    scale12_kernel<<<CDIV(N * 12, B), B, 0, sd>>>(Wout, S_.dinvW, S_.ws12, N);
    gcn_fused_kernel<<<2 * nb1W, 256, 0, sd>>>(S_.offW, S_.csrW, S_.dinvW, S_.ws12,
                                               wg0w, wg0b, S_.x2sb, wg1w, wg1b,
                                               Wih, bih, bhh, S_.xgW, N, nb1W, S_.syncW);
    cudaEventRecord(S_.evJ, sd);

    // side stream (after join point): persistent H-prefix worker for the whole loop
    prefix_persist_kernel<<<1, 192, 0, sd>>>(S_.xgH, Whh, S_.stateArr, dHw, dHb, Hout, K);
    cudaEventRecord(S_.evP, sd);

    // main stream: H setup + H-GCN + chunked H-full scan (+denseH, dproj cache)
    cvt_deg_kernel<<<gE, B>>>(HA, S_.srcH, S_.dstH, S_.idegH, E, S_.flags + 0);
    scan_dinv_kernel<<<1, 1024>>>(S_.idegH, S_.offH, S_.curH, S_.dinvH, M);
    csrfill_kernel<<<gE, B>>>(S_.srcH, S_.dstH, S_.curH, S_.csrH, E);
    cudaMemcpyAsync(Hout, H, (size_t)M * 10 * sizeof(float), cudaMemcpyDeviceToDevice);
    scale12_kernel<<<CDIV(M * 12, B), B>>>(H, S_.dinvH, S_.hs12, M);
    gcn_fused_kernel<<<2 * nb1H, 256>>>(S_.offH, S_.csrH, S_.dinvH, S_.hs12,
                                        hg0w, hg0b, S_.x2s, hg1w, hg1b,
                                        Wih, bih, bhh, S_.xgH, M, nb1H, S_.syncH);
    lstm_chunk_kernel<<<CM, 192>>>(S_.xgH, Whh, S_.state0, S_.stateHend, M, CHL, BURN,
                                   dHw, dHb, Hout, S_.dproj, nullptr, nullptr, 0);

    // join W-GCN(0) before loop
    cudaStreamWaitEvent(0, S_.evJ, 0);

    // --- T=10 iterations, pure main-stream chain ---
    for (int it = 0; it < 10; it++) {
        lstm_chunk_kernel<<<CN, 192>>>(S_.xgW, Whh, S_.stateHend,
                                       S_.stateArr + it * 2 * NH, N, CHL, BURN,
                                       dWw, dWb, Wout, nullptr,
                                       (it < 9) ? S_.ws12 : nullptr, S_.dinvW,
                                       (it < 9) ? (it + 1) : 0);
        if (it < 9)
            gcn_fused_kernel<<<2 * nb1W, 256>>>(S_.offW, S_.csrW, S_.dinvW, S_.ws12,
                                                wg0w, wg0b, S_.x2sb, wg1w, wg1b,
                                                Wih, bih, bhh, S_.xgW, N, nb1W, S_.syncW);
    }

    // join the persistent prefix worker, then tail rows of Hout
    cudaStreamWaitEvent(0, S_.evP, 0);
    if (M > K)
        tail_kernel<<<CDIV((M - K) * 10, B), B>>>(Hout, S_.dproj, K * 10, M * 10);
}